// round 1
// baseline (speedup 1.0000x reference)
#include <cuda_runtime.h>

#define NMAX 50000
#define HDIM 256
#define DIN  128

// Scratch (static __device__ arrays — no allocation allowed)
__device__ float g_feat[NMAX * HDIM];   // current node features / aggregation dest
__device__ float g_hw[NMAX * HDIM];     // h @ W (pre-scaled by dinv[row])
__device__ float g_dinv[NMAX];
__device__ int   g_deg[NMAX];

// ---------------------------------------------------------------------------
// degree / norm
// ---------------------------------------------------------------------------
__global__ void deg_zero_k(int* deg, int n) {
    int i = blockIdx.x * blockDim.x + threadIdx.x;
    if (i < n) deg[i] = 0;
}

__global__ void deg_count_k(const int* __restrict__ dst, int* deg, int e) {
    int i = blockIdx.x * blockDim.x + threadIdx.x;
    if (i < e) atomicAdd(&deg[dst[i]], 1);
}

__global__ void dinv_k(const int* __restrict__ deg, float* dinv, int n) {
    int i = blockIdx.x * blockDim.x + threadIdx.x;
    if (i < n) dinv[i] = rsqrtf((float)(deg[i] + 1));  // +1 self-loop
}

// ---------------------------------------------------------------------------
// SGEMM: C[M,N] = A[M,K] @ B[K,N], epilogue: * rowscale[row] (opt) + bias[col] (opt)
// BM=BN=64, BK=16, 256 threads, 4x4 per thread
// ---------------------------------------------------------------------------
#define BM 64
#define BN 64
#define BK 16
#define TM 4
#define TN 4

__global__ __launch_bounds__(256)
void sgemm_k(const float* __restrict__ A, const float* __restrict__ B,
             const float* __restrict__ bias, const float* __restrict__ rowscale,
             float* __restrict__ C, int M, int K, int N) {
    __shared__ float As[BK][BM];
    __shared__ float Bs[BK][BN];

    int tx   = threadIdx.x;
    int row0 = blockIdx.x * BM;
    int col0 = blockIdx.y * BN;
    int tr   = (tx / 16) * TM;
    int tc   = (tx % 16) * TN;

    float acc[TM][TN] = {};

    for (int k0 = 0; k0 < K; k0 += BK) {
        // load A tile (BM x BK), transposed into As[k][m]
        #pragma unroll
        for (int i = tx; i < BM * BK; i += 256) {
            int r = i / BK, c = i % BK;
            int gr = row0 + r;
            As[c][r] = (gr < M) ? A[(size_t)gr * K + k0 + c] : 0.f;
        }
        // load B tile (BK x BN)
        #pragma unroll
        for (int i = tx; i < BK * BN; i += 256) {
            int r = i / BN, c = i % BN;
            Bs[r][c] = B[(size_t)(k0 + r) * N + col0 + c];
        }
        __syncthreads();

        #pragma unroll
        for (int k = 0; k < BK; k++) {
            float a[TM], b[TN];
            #pragma unroll
            for (int i = 0; i < TM; i++) a[i] = As[k][tr + i];
            #pragma unroll
            for (int j = 0; j < TN; j++) b[j] = Bs[k][tc + j];
            #pragma unroll
            for (int i = 0; i < TM; i++)
                #pragma unroll
                for (int j = 0; j < TN; j++) acc[i][j] += a[i] * b[j];
        }
        __syncthreads();
    }

    #pragma unroll
    for (int i = 0; i < TM; i++) {
        int gr = row0 + tr + i;
        if (gr >= M) continue;
        float s = rowscale ? rowscale[gr] : 1.f;
        #pragma unroll
        for (int j = 0; j < TN; j++) {
            int gc = col0 + tc + j;
            float v = acc[i][j] * s;
            if (bias) v += bias[gc];
            C[(size_t)gr * N + gc] = v;
        }
    }
}

// ---------------------------------------------------------------------------
// self-loop init: agg[i,:] = hws[i,:] * dinv[i]     (hws already scaled by dinv[i])
// ---------------------------------------------------------------------------
__global__ void self_loop_k(const float* __restrict__ hws, const float* __restrict__ dinv,
                            float* __restrict__ agg, int n) {
    int i = blockIdx.x * blockDim.x + threadIdx.x;       // float4 index
    int total = n * (HDIM / 4);
    if (i >= total) return;
    int row = i / (HDIM / 4);
    float s = dinv[row];
    float4 v = ((const float4*)hws)[i];
    v.x *= s; v.y *= s; v.z *= s; v.w *= s;
    ((float4*)agg)[i] = v;
}

// ---------------------------------------------------------------------------
// edge scatter: agg[dst,:] += hws[src,:] * dinv[dst]   (hws pre-scaled by dinv[src])
// 64 threads per edge, each handles one float4
// ---------------------------------------------------------------------------
__global__ __launch_bounds__(256)
void edge_scatter_k(const float* __restrict__ hws, const int* __restrict__ src,
                    const int* __restrict__ dst, const float* __restrict__ dinv,
                    float* __restrict__ agg, int e) {
    int idx  = blockIdx.x * blockDim.x + threadIdx.x;
    int edge = idx >> 6;
    int lane = idx & 63;
    if (edge >= e) return;
    int s = src[edge], d = dst[edge];
    float nd = dinv[d];
    float4 v = ((const float4*)(hws + (size_t)s * HDIM))[lane];
    float* o = agg + (size_t)d * HDIM + lane * 4;
    atomicAdd(o + 0, v.x * nd);
    atomicAdd(o + 1, v.y * nd);
    atomicAdd(o + 2, v.z * nd);
    atomicAdd(o + 3, v.w * nd);
}

// ---------------------------------------------------------------------------
// bias + relu (in place), vectorized
// ---------------------------------------------------------------------------
__global__ void bias_relu_k(float* __restrict__ agg, const float* __restrict__ bias, int n) {
    int i = blockIdx.x * blockDim.x + threadIdx.x;       // float4 index
    int total = n * (HDIM / 4);
    if (i >= total) return;
    int cb = i & (HDIM / 4 - 1);
    float4 b = ((const float4*)bias)[cb];
    float4 v = ((float4*)agg)[i];
    v.x = fmaxf(v.x + b.x, 0.f);
    v.y = fmaxf(v.y + b.y, 0.f);
    v.z = fmaxf(v.z + b.z, 0.f);
    v.w = fmaxf(v.w + b.w, 0.f);
    ((float4*)agg)[i] = v;
}

// ---------------------------------------------------------------------------
// decoder: out[i] = dot(feat[i,:], w) + b    one warp per node
// ---------------------------------------------------------------------------
__global__ __launch_bounds__(256)
void decoder_k(const float* __restrict__ feat, const float* __restrict__ w,
               const float* __restrict__ b, float* __restrict__ out, int n) {
    int gwarp = (blockIdx.x * blockDim.x + threadIdx.x) >> 5;
    int lane  = threadIdx.x & 31;
    if (gwarp >= n) return;
    const float4* f  = (const float4*)(feat + (size_t)gwarp * HDIM);
    const float4* wv = (const float4*)w;
    float acc = 0.f;
    #pragma unroll
    for (int j = lane; j < HDIM / 4; j += 32) {
        float4 a = f[j], ww = wv[j];
        acc += a.x * ww.x + a.y * ww.y + a.z * ww.z + a.w * ww.w;
    }
    #pragma unroll
    for (int o = 16; o; o >>= 1) acc += __shfl_xor_sync(0xffffffffu, acc, o);
    if (lane == 0) out[gwarp] = acc + b[0];
}

// ---------------------------------------------------------------------------
// launch
// ---------------------------------------------------------------------------
extern "C" void kernel_launch(void* const* d_in, const int* in_sizes, int n_in,
                              void* d_out, int out_size) {
    const float* x     = (const float*)d_in[0];
    const int*   ei    = (const int*)  d_in[1];
    const float* enc_W = (const float*)d_in[2];
    const float* enc_b = (const float*)d_in[3];
    const float* W[3]  = {(const float*)d_in[4], (const float*)d_in[6], (const float*)d_in[8]};
    const float* bb[3] = {(const float*)d_in[5], (const float*)d_in[7], (const float*)d_in[9]};
    const float* dec_W = (const float*)d_in[10];
    const float* dec_b = (const float*)d_in[11];
    float* out = (float*)d_out;

    int n = in_sizes[0] / DIN;
    int e = in_sizes[1] / 2;
    const int* src = ei;
    const int* dst = ei + e;

    float *feat, *hw, *dinv; int* deg;
    cudaGetSymbolAddress((void**)&feat, g_feat);
    cudaGetSymbolAddress((void**)&hw,   g_hw);
    cudaGetSymbolAddress((void**)&dinv, g_dinv);
    cudaGetSymbolAddress((void**)&deg,  g_deg);

    // degrees + norm (once; shared by all 3 convs)
    deg_zero_k<<<(n + 255) / 256, 256>>>(deg, n);
    deg_count_k<<<(e + 255) / 256, 256>>>(dst, deg, e);
    dinv_k<<<(n + 255) / 256, 256>>>(deg, dinv, n);

    dim3 gemm_block(256);
    dim3 gemm_grid((n + BM - 1) / BM, HDIM / BN);

    // encoder: feat = x @ enc_W + enc_b
    sgemm_k<<<gemm_grid, gemm_block>>>(x, enc_W, enc_b, nullptr, feat, n, DIN, HDIM);

    int vec4  = n * (HDIM / 4);
    int vgrid = (vec4 + 255) / 256;
    int egrid = ((e * 64) + 255) / 256;

    for (int l = 0; l < 3; l++) {
        // hw = (feat @ Wl) * dinv[row]
        sgemm_k<<<gemm_grid, gemm_block>>>(feat, W[l], nullptr, dinv, hw, n, HDIM, HDIM);
        // feat = hw * dinv[row]  (self-loop: hw already has one dinv factor)
        self_loop_k<<<vgrid, 256>>>(hw, dinv, feat, n);
        // feat[dst] += hw[src] * dinv[dst]
        edge_scatter_k<<<egrid, 256>>>(hw, src, dst, dinv, feat, e);
        // feat = relu(feat + b)
        bias_relu_k<<<vgrid, 256>>>(feat, bb[l], n);
    }

    // decoder
    decoder_k<<<(n * 32 + 255) / 256, 256>>>(feat, dec_W, dec_b, out, n);
}

// round 2
// speedup vs baseline: 2.3417x; 2.3417x over previous
#include <cuda_runtime.h>

#define NMAX 50000
#define EMAX 800000
#define HDIM 256
#define DIN  128

// Scratch (static __device__ arrays — no allocation allowed)
__device__ float g_feat[NMAX * HDIM];     // current node features
__device__ float g_hw[NMAX * HDIM];       // (feat @ W) * dinv[row]
__device__ float g_dinv[NMAX];
__device__ int   g_deg[NMAX];
__device__ int   g_row_start[NMAX + 1];
__device__ int   g_cursor[NMAX];
__device__ int   g_csr_src[EMAX];

// ---------------------------------------------------------------------------
// degree / norm
// ---------------------------------------------------------------------------
__global__ void deg_zero_k(int* deg, int n) {
    int i = blockIdx.x * blockDim.x + threadIdx.x;
    if (i < n) deg[i] = 0;
}

__global__ void deg_count_k(const int* __restrict__ dst, int* deg, int e) {
    int i = blockIdx.x * blockDim.x + threadIdx.x;
    if (i < e) atomicAdd(&deg[dst[i]], 1);
}

__global__ void dinv_k(const int* __restrict__ deg, float* dinv, int n) {
    int i = blockIdx.x * blockDim.x + threadIdx.x;
    if (i < n) dinv[i] = rsqrtf((float)(deg[i] + 1));  // +1 self-loop
}

// ---------------------------------------------------------------------------
// single-block exclusive scan over deg -> row_start (and cursor copy)
// ---------------------------------------------------------------------------
__global__ void scan_k(const int* __restrict__ deg, int* row_start, int* cursor, int n) {
    __shared__ int sm[1024];
    __shared__ int carry_s;
    int tid = threadIdx.x;
    if (tid == 0) carry_s = 0;
    __syncthreads();
    for (int base = 0; base < n; base += 1024) {
        int i = base + tid;
        int v = (i < n) ? deg[i] : 0;
        sm[tid] = v;
        __syncthreads();
        #pragma unroll
        for (int off = 1; off < 1024; off <<= 1) {
            int t = (tid >= off) ? sm[tid - off] : 0;
            __syncthreads();
            sm[tid] += t;
            __syncthreads();
        }
        int carry = carry_s;
        int excl = carry + sm[tid] - v;
        if (i < n) { row_start[i] = excl; cursor[i] = excl; }
        __syncthreads();
        if (tid == 1023) carry_s = carry + sm[1023];
        __syncthreads();
    }
    if (tid == 0) row_start[n] = carry_s;
}

__global__ void fill_csr_k(const int* __restrict__ src, const int* __restrict__ dst,
                           int* cursor, int* csr_src, int e) {
    int i = blockIdx.x * blockDim.x + threadIdx.x;
    if (i < e) {
        int d = dst[i];
        int pos = atomicAdd(&cursor[d], 1);
        csr_src[pos] = src[i];
    }
}

// ---------------------------------------------------------------------------
// SGEMM: C[M,N] = A[M,K] @ B[K,N]; epilogue * rowscale[row] (opt) + bias[col] (opt)
// 128x128 tile, BK=16, 256 threads, 8x8 per thread, float4 everywhere
// ---------------------------------------------------------------------------
#define BM 128
#define BN 128
#define BK 16

__global__ __launch_bounds__(256, 2)
void sgemm_k(const float* __restrict__ A, const float* __restrict__ B,
             const float* __restrict__ bias, const float* __restrict__ rowscale,
             float* __restrict__ C, int M, int K, int N) {
    __shared__ float As[BK][BM + 4];   // transposed A tile (padded)
    __shared__ float Bs[BK][BN];

    int tx   = threadIdx.x;
    int row0 = blockIdx.x * BM;
    int col0 = blockIdx.y * BN;
    int tr   = (tx / 16) * 8;
    int tc   = (tx % 16) * 8;

    int aRow  = tx / 4;        // 0..63
    int aCol4 = (tx % 4) * 4;  // 0,4,8,12
    int bRow  = tx / 32;       // 0..7
    int bCol  = (tx % 32) * 4;

    float acc[8][8] = {};

    for (int k0 = 0; k0 < K; k0 += BK) {
        // A tile: rows aRow and aRow+64, 4 floats each, transposed into As
        #pragma unroll
        for (int half = 0; half < 2; half++) {
            int r  = aRow + half * 64;
            int gr = row0 + r;
            float4 v = make_float4(0.f, 0.f, 0.f, 0.f);
            if (gr < M) v = *(const float4*)&A[(size_t)gr * K + k0 + aCol4];
            As[aCol4 + 0][r] = v.x;
            As[aCol4 + 1][r] = v.y;
            As[aCol4 + 2][r] = v.z;
            As[aCol4 + 3][r] = v.w;
        }
        // B tile: rows bRow and bRow+8
        #pragma unroll
        for (int half = 0; half < 2; half++) {
            int r = bRow + half * 8;
            float4 v = *(const float4*)&B[(size_t)(k0 + r) * N + col0 + bCol];
            *(float4*)&Bs[r][bCol] = v;
        }
        __syncthreads();

        #pragma unroll
        for (int k = 0; k < BK; k++) {
            float a[8], b[8];
            *(float4*)&a[0] = *(const float4*)&As[k][tr];
            *(float4*)&a[4] = *(const float4*)&As[k][tr + 4];
            *(float4*)&b[0] = *(const float4*)&Bs[k][tc];
            *(float4*)&b[4] = *(const float4*)&Bs[k][tc + 4];
            #pragma unroll
            for (int i = 0; i < 8; i++)
                #pragma unroll
                for (int j = 0; j < 8; j++)
                    acc[i][j] += a[i] * b[j];
        }
        __syncthreads();
    }

    #pragma unroll
    for (int i = 0; i < 8; i++) {
        int gr = row0 + tr + i;
        if (gr >= M) continue;
        float s = rowscale ? rowscale[gr] : 1.f;
        #pragma unroll
        for (int j4 = 0; j4 < 2; j4++) {
            int gc = col0 + tc + j4 * 4;
            float4 v;
            v.x = acc[i][j4 * 4 + 0] * s;
            v.y = acc[i][j4 * 4 + 1] * s;
            v.z = acc[i][j4 * 4 + 2] * s;
            v.w = acc[i][j4 * 4 + 3] * s;
            if (bias) {
                float4 b = *(const float4*)&bias[gc];
                v.x += b.x; v.y += b.y; v.z += b.z; v.w += b.w;
            }
            *(float4*)&C[(size_t)gr * N + gc] = v;
        }
    }
}

// ---------------------------------------------------------------------------
// GCN aggregation (CSR gather, no atomics):
//   out[d,c] = relu( dinv[d] * (hw[d,c] + sum_{s in in(d)} hw[s,c]) + bias[c] )
// One block (256 threads) per node, one column per thread.
// If do_dec: instead of writing the feature row, dot with decW and emit scalar.
// ---------------------------------------------------------------------------
__global__ __launch_bounds__(256)
void gcn_gather_k(const float* __restrict__ hw, const int* __restrict__ row_start,
                  const int* __restrict__ csr_src, const float* __restrict__ dinv,
                  const float* __restrict__ bias, float* __restrict__ outfeat,
                  const float* __restrict__ decW, const float* __restrict__ decb,
                  float* __restrict__ decout, int do_dec) {
    int node = blockIdx.x;
    int tid  = threadIdx.x;
    __shared__ int s_src[64];

    int beg = row_start[node];
    int end = row_start[node + 1];

    float acc = hw[(size_t)node * HDIM + tid];   // self-loop term
    for (int eb = beg; eb < end; eb += 64) {
        int cnt = min(64, end - eb);
        if (tid < cnt) s_src[tid] = csr_src[eb + tid];
        __syncthreads();
        #pragma unroll 4
        for (int j = 0; j < cnt; j++)
            acc += hw[(size_t)s_src[j] * HDIM + tid];
        __syncthreads();
    }

    float v = fmaxf(acc * dinv[node] + bias[tid], 0.f);

    if (!do_dec) {
        outfeat[(size_t)node * HDIM + tid] = v;
    } else {
        __shared__ float red[256];
        red[tid] = v * decW[tid];
        __syncthreads();
        #pragma unroll
        for (int off = 128; off > 0; off >>= 1) {
            if (tid < off) red[tid] += red[tid + off];
            __syncthreads();
        }
        if (tid == 0) decout[node] = red[0] + decb[0];
    }
}

// ---------------------------------------------------------------------------
// launch
// ---------------------------------------------------------------------------
extern "C" void kernel_launch(void* const* d_in, const int* in_sizes, int n_in,
                              void* d_out, int out_size) {
    const float* x     = (const float*)d_in[0];
    const int*   ei    = (const int*)  d_in[1];
    const float* enc_W = (const float*)d_in[2];
    const float* enc_b = (const float*)d_in[3];
    const float* W[3]  = {(const float*)d_in[4], (const float*)d_in[6], (const float*)d_in[8]};
    const float* bb[3] = {(const float*)d_in[5], (const float*)d_in[7], (const float*)d_in[9]};
    const float* dec_W = (const float*)d_in[10];
    const float* dec_b = (const float*)d_in[11];
    float* out = (float*)d_out;

    int n = in_sizes[0] / DIN;
    int e = in_sizes[1] / 2;
    const int* src = ei;
    const int* dst = ei + e;

    float *feat, *hw, *dinv;
    int *deg, *row_start, *cursor, *csr_src;
    cudaGetSymbolAddress((void**)&feat,      g_feat);
    cudaGetSymbolAddress((void**)&hw,        g_hw);
    cudaGetSymbolAddress((void**)&dinv,      g_dinv);
    cudaGetSymbolAddress((void**)&deg,       g_deg);
    cudaGetSymbolAddress((void**)&row_start, g_row_start);
    cudaGetSymbolAddress((void**)&cursor,    g_cursor);
    cudaGetSymbolAddress((void**)&csr_src,   g_csr_src);

    // CSR build + norm (once; shared by all 3 convs)
    deg_zero_k <<<(n + 255) / 256, 256>>>(deg, n);
    deg_count_k<<<(e + 255) / 256, 256>>>(dst, deg, e);
    dinv_k     <<<(n + 255) / 256, 256>>>(deg, dinv, n);
    scan_k     <<<1, 1024>>>(deg, row_start, cursor, n);
    fill_csr_k <<<(e + 255) / 256, 256>>>(src, dst, cursor, csr_src, e);

    dim3 gemm_block(256);
    dim3 gemm_grid((n + BM - 1) / BM, HDIM / BN);

    // encoder: feat = x @ enc_W + enc_b
    sgemm_k<<<gemm_grid, gemm_block>>>(x, enc_W, enc_b, nullptr, feat, n, DIN, HDIM);

    for (int l = 0; l < 3; l++) {
        // hw = (feat @ Wl) * dinv[row]
        sgemm_k<<<gemm_grid, gemm_block>>>(feat, W[l], nullptr, dinv, hw, n, HDIM, HDIM);
        // gather + self-loop + bias + relu (+ fused decoder on last layer)
        int last = (l == 2);
        gcn_gather_k<<<n, 256>>>(hw, row_start, csr_src, dinv, bb[l],
                                 feat, dec_W, dec_b, out, last);
    }
}

// round 11
// speedup vs baseline: 3.7377x; 1.5962x over previous
#include <cuda_runtime.h>
#include <cstdint>

#define NMAX 50000
#define EMAX 800000
#define HDIM 256
#define DIN  128

// Scratch (static __device__ arrays — no allocation allowed)
__device__ float g_feat[NMAX * HDIM];
__device__ float g_hw[NMAX * HDIM];
__device__ float g_dinv[NMAX];
__device__ int   g_deg[NMAX];
__device__ int   g_row_start[NMAX + 1];
__device__ int   g_cursor[NMAX];
__device__ int   g_csr_src[EMAX];
__device__ int   g_bsum[64];

// ---------------------------------------------------------------------------
// degree / norm
// ---------------------------------------------------------------------------
__global__ void deg_zero_k(int* deg, int n) {
    int i = blockIdx.x * blockDim.x + threadIdx.x;
    if (i < n) deg[i] = 0;
}

__global__ void deg_count_k(const int* __restrict__ dst, int* deg, int e) {
    int i = blockIdx.x * blockDim.x + threadIdx.x;
    if (i < e) atomicAdd(&deg[dst[i]], 1);
}

__global__ void dinv_k(const int* __restrict__ deg, float* dinv, int n) {
    int i = blockIdx.x * blockDim.x + threadIdx.x;
    if (i < n) dinv[i] = rsqrtf((float)(deg[i] + 1));  // +1 self-loop
}

// ---------------------------------------------------------------------------
// 3-phase parallel exclusive scan (deg -> row_start, cursor)
// ---------------------------------------------------------------------------
__global__ void block_sum_k(const int* __restrict__ deg, int* bsum, int n) {
    __shared__ int sm[1024];
    int t = threadIdx.x;
    int i = blockIdx.x * 1024 + t;
    sm[t] = (i < n) ? deg[i] : 0;
    __syncthreads();
    #pragma unroll
    for (int off = 512; off > 0; off >>= 1) {
        if (t < off) sm[t] += sm[t + off];
        __syncthreads();
    }
    if (t == 0) bsum[blockIdx.x] = sm[0];
}

__global__ void scan_bsum_k(int* bsum, int nb) {  // single block, nb <= 1024
    __shared__ int sm[1024];
    int t = threadIdx.x;
    int v0 = (t < nb) ? bsum[t] : 0;
    sm[t] = v0;
    __syncthreads();
    #pragma unroll
    for (int off = 1; off < 1024; off <<= 1) {
        int u = (t >= off) ? sm[t - off] : 0;
        __syncthreads();
        sm[t] += u;
        __syncthreads();
    }
    if (t < nb) bsum[t] = sm[t] - v0;   // exclusive
}

__global__ void scan_final_k(const int* __restrict__ deg, const int* __restrict__ bsum,
                             int* row_start, int* cursor, int n) {
    __shared__ int sm[1024];
    int t = threadIdx.x;
    int i = blockIdx.x * 1024 + t;
    int v = (i < n) ? deg[i] : 0;
    sm[t] = v;
    __syncthreads();
    #pragma unroll
    for (int off = 1; off < 1024; off <<= 1) {
        int u = (t >= off) ? sm[t - off] : 0;
        __syncthreads();
        sm[t] += u;
        __syncthreads();
    }
    int excl = bsum[blockIdx.x] + sm[t] - v;
    if (i < n) {
        row_start[i] = excl;
        cursor[i]    = excl;
        if (i == n - 1) row_start[n] = excl + v;
    }
}

__global__ void fill_csr_k(const int* __restrict__ src, const int* __restrict__ dst,
                           int* cursor, int* csr_src, int e) {
    int i = blockIdx.x * blockDim.x + threadIdx.x;
    if (i < e) {
        int d = dst[i];
        int pos = atomicAdd(&cursor[d], 1);
        csr_src[pos] = src[i];
    }
}

// ---------------------------------------------------------------------------
// tf32 tensor-core GEMM: C[M,N] = A[M,K] @ B[K,N]
// epilogue: * rowscale[row] (opt) + bias[col] (opt)
// CTA tile 128x64, BK=32, 256 threads (8 warps, warp tile 32x32)
// mma.sync.aligned.m16n8k8.row.col.f32.tf32.tf32.f32
// ---------------------------------------------------------------------------
#define GBM 128
#define GBN 64
#define GBK 32
#define A_ST 36   // smem row stride for A (floats): conflict-free frag loads
#define B_ST 72   // smem row stride for B (floats)

__device__ __forceinline__ uint32_t f2tf32(float x) {
    uint32_t r;
    asm("cvt.rna.tf32.f32 %0, %1;" : "=r"(r) : "f"(x));
    return r;
}

__device__ __forceinline__ void mma_tf32(float& c0, float& c1, float& c2, float& c3,
                                         uint32_t a0, uint32_t a1, uint32_t a2, uint32_t a3,
                                         uint32_t b0, uint32_t b1) {
    asm volatile(
        "mma.sync.aligned.m16n8k8.row.col.f32.tf32.tf32.f32 "
        "{%0,%1,%2,%3}, {%4,%5,%6,%7}, {%8,%9}, {%0,%1,%2,%3};\n"
        : "+f"(c0), "+f"(c1), "+f"(c2), "+f"(c3)
        : "r"(a0), "r"(a1), "r"(a2), "r"(a3), "r"(b0), "r"(b1));
}

__global__ __launch_bounds__(256, 2)
void tgemm_k(const float* __restrict__ A, const float* __restrict__ B,
             const float* __restrict__ bias, const float* __restrict__ rowscale,
             float* __restrict__ C, int M, int K, int N) {
    __shared__ uint32_t As[GBM * A_ST];   // As[row][k], row-major, stride 36
    __shared__ uint32_t Bs[GBK * B_ST];   // Bs[k][n],  stride 72

    int tx     = threadIdx.x;
    int wid    = tx >> 5;
    int lane   = tx & 31;
    int g      = lane >> 2;        // group id 0..7
    int tg     = lane & 3;         // thread-in-group 0..3
    int warp_m = (wid & 3) * 32;   // warp row offset
    int warp_n = (wid >> 2) * 32;  // warp col offset

    int row0 = blockIdx.x * GBM;
    int col0 = blockIdx.y * GBN;

    // global load mapping
    int aRow  = tx >> 3;                // 0..31 base
    int aCol4 = (tx & 7) * 4;
    int bRow  = tx >> 4;                // 0..15 base
    int bCol4 = (tx & 15) * 4;

    float acc[2][4][4];
    #pragma unroll
    for (int i = 0; i < 2; i++)
        #pragma unroll
        for (int j = 0; j < 4; j++)
            #pragma unroll
            for (int q = 0; q < 4; q++) acc[i][j][q] = 0.f;

    int nT = K / GBK;

    float4 aReg[4];
    float4 bReg[2];

    // prologue: load tile 0
    {
        int k0 = 0;
        #pragma unroll
        for (int i = 0; i < 4; i++) {
            int r  = aRow + i * 32;
            int gr = row0 + r;
            aReg[i] = (gr < M) ? *(const float4*)&A[(size_t)gr * K + k0 + aCol4]
                               : make_float4(0.f, 0.f, 0.f, 0.f);
        }
        #pragma unroll
        for (int i = 0; i < 2; i++) {
            int r = bRow + i * 16;
            bReg[i] = *(const float4*)&B[(size_t)(k0 + r) * N + col0 + bCol4];
        }
    }

    for (int t = 0; t < nT; t++) {
        // store current tile to smem (with tf32 conversion)
        #pragma unroll
        for (int i = 0; i < 4; i++) {
            int r = aRow + i * 32;
            uint32_t* p = &As[r * A_ST + aCol4];
            p[0] = f2tf32(aReg[i].x);
            p[1] = f2tf32(aReg[i].y);
            p[2] = f2tf32(aReg[i].z);
            p[3] = f2tf32(aReg[i].w);
        }
        #pragma unroll
        for (int i = 0; i < 2; i++) {
            int r = bRow + i * 16;
            uint32_t* p = &Bs[r * B_ST + bCol4];
            p[0] = f2tf32(bReg[i].x);
            p[1] = f2tf32(bReg[i].y);
            p[2] = f2tf32(bReg[i].z);
            p[3] = f2tf32(bReg[i].w);
        }
        __syncthreads();

        // prefetch next tile into registers
        if (t + 1 < nT) {
            int k0 = (t + 1) * GBK;
            #pragma unroll
            for (int i = 0; i < 4; i++) {
                int r  = aRow + i * 32;
                int gr = row0 + r;
                aReg[i] = (gr < M) ? *(const float4*)&A[(size_t)gr * K + k0 + aCol4]
                                   : make_float4(0.f, 0.f, 0.f, 0.f);
            }
            #pragma unroll
            for (int i = 0; i < 2; i++) {
                int r = bRow + i * 16;
                bReg[i] = *(const float4*)&B[(size_t)(k0 + r) * N + col0 + bCol4];
            }
        }

        // compute over smem tile
        #pragma unroll
        for (int ks = 0; ks < 4; ks++) {
            int kk = ks * 8;
            uint32_t af[2][4];
            #pragma unroll
            for (int mt = 0; mt < 2; mt++) {
                int r = warp_m + mt * 16 + g;
                af[mt][0] = As[r * A_ST + kk + tg];
                af[mt][1] = As[(r + 8) * A_ST + kk + tg];
                af[mt][2] = As[r * A_ST + kk + tg + 4];
                af[mt][3] = As[(r + 8) * A_ST + kk + tg + 4];
            }
            uint32_t bf[4][2];
            #pragma unroll
            for (int nt = 0; nt < 4; nt++) {
                int c = warp_n + nt * 8 + g;
                bf[nt][0] = Bs[(kk + tg) * B_ST + c];
                bf[nt][1] = Bs[(kk + tg + 4) * B_ST + c];
            }
            #pragma unroll
            for (int mt = 0; mt < 2; mt++)
                #pragma unroll
                for (int nt = 0; nt < 4; nt++)
                    mma_tf32(acc[mt][nt][0], acc[mt][nt][1], acc[mt][nt][2], acc[mt][nt][3],
                             af[mt][0], af[mt][1], af[mt][2], af[mt][3],
                             bf[nt][0], bf[nt][1]);
        }
        __syncthreads();
    }

    // epilogue
    #pragma unroll
    for (int mt = 0; mt < 2; mt++) {
        int gr0 = row0 + warp_m + mt * 16 + g;
        int gr1 = gr0 + 8;
        float s0 = 1.f, s1 = 1.f;
        if (rowscale) {
            if (gr0 < M) s0 = rowscale[gr0];
            if (gr1 < M) s1 = rowscale[gr1];
        }
        #pragma unroll
        for (int nt = 0; nt < 4; nt++) {
            int gc = col0 + warp_n + nt * 8 + 2 * tg;
            float bx = 0.f, by = 0.f;
            if (bias) { bx = bias[gc]; by = bias[gc + 1]; }
            if (gr0 < M) {
                float2 v;
                v.x = acc[mt][nt][0] * s0 + bx;
                v.y = acc[mt][nt][1] * s0 + by;
                *(float2*)&C[(size_t)gr0 * N + gc] = v;
            }
            if (gr1 < M) {
                float2 v;
                v.x = acc[mt][nt][2] * s1 + bx;
                v.y = acc[mt][nt][3] * s1 + by;
                *(float2*)&C[(size_t)gr1 * N + gc] = v;
            }
        }
    }
}

// ---------------------------------------------------------------------------
// GCN aggregation (CSR gather, no atomics):
//   out[d,c] = relu( dinv[d] * (hw[d,c] + sum_{s in in(d)} hw[s,c]) + bias[c] )
// One block (256 threads) per node, one column per thread.
// ---------------------------------------------------------------------------
__global__ __launch_bounds__(256)
void gcn_gather_k(const float* __restrict__ hw, const int* __restrict__ row_start,
                  const int* __restrict__ csr_src, const float* __restrict__ dinv,
                  const float* __restrict__ bias, float* __restrict__ outfeat,
                  const float* __restrict__ decW, const float* __restrict__ decb,
                  float* __restrict__ decout, int do_dec) {
    int node = blockIdx.x;
    int tid  = threadIdx.x;
    __shared__ int s_src[64];

    int beg = row_start[node];
    int end = row_start[node + 1];

    float acc = hw[(size_t)node * HDIM + tid];   // self-loop term
    for (int eb = beg; eb < end; eb += 64) {
        int cnt = min(64, end - eb);
        if (tid < cnt) s_src[tid] = csr_src[eb + tid];
        __syncthreads();
        #pragma unroll 4
        for (int j = 0; j < cnt; j++)
            acc += hw[(size_t)s_src[j] * HDIM + tid];
        __syncthreads();
    }

    float v = fmaxf(acc * dinv[node] + bias[tid], 0.f);

    if (!do_dec) {
        outfeat[(size_t)node * HDIM + tid] = v;
    } else {
        __shared__ float red[256];
        red[tid] = v * decW[tid];
        __syncthreads();
        #pragma unroll
        for (int off = 128; off > 0; off >>= 1) {
            if (tid < off) red[tid] += red[tid + off];
            __syncthreads();
        }
        if (tid == 0) decout[node] = red[0] + decb[0];
    }
}

// ---------------------------------------------------------------------------
// launch
// ---------------------------------------------------------------------------
extern "C" void kernel_launch(void* const* d_in, const int* in_sizes, int n_in,
                              void* d_out, int out_size) {
    const float* x     = (const float*)d_in[0];
    const int*   ei    = (const int*)  d_in[1];
    const float* enc_W = (const float*)d_in[2];
    const float* enc_b = (const float*)d_in[3];
    const float* W[3]  = {(const float*)d_in[4], (const float*)d_in[6], (const float*)d_in[8]};
    const float* bb[3] = {(const float*)d_in[5], (const float*)d_in[7], (const float*)d_in[9]};
    const float* dec_W = (const float*)d_in[10];
    const float* dec_b = (const float*)d_in[11];
    float* out = (float*)d_out;

    int n = in_sizes[0] / DIN;
    int e = in_sizes[1] / 2;
    const int* src = ei;
    const int* dst = ei + e;

    float *feat, *hw, *dinv;
    int *deg, *row_start, *cursor, *csr_src, *bsum;
    cudaGetSymbolAddress((void**)&feat,      g_feat);
    cudaGetSymbolAddress((void**)&hw,        g_hw);
    cudaGetSymbolAddress((void**)&dinv,      g_dinv);
    cudaGetSymbolAddress((void**)&deg,       g_deg);
    cudaGetSymbolAddress((void**)&row_start, g_row_start);
    cudaGetSymbolAddress((void**)&cursor,    g_cursor);
    cudaGetSymbolAddress((void**)&csr_src,   g_csr_src);
    cudaGetSymbolAddress((void**)&bsum,      g_bsum);

    int nb = (n + 1023) / 1024;

    // CSR build + norm (once; shared by all 3 convs)
    deg_zero_k  <<<(n + 255) / 256, 256>>>(deg, n);
    deg_count_k <<<(e + 255) / 256, 256>>>(dst, deg, e);
    dinv_k      <<<(n + 255) / 256, 256>>>(deg, dinv, n);
    block_sum_k <<<nb, 1024>>>(deg, bsum, n);
    scan_bsum_k <<<1, 1024>>>(bsum, nb);
    scan_final_k<<<nb, 1024>>>(deg, bsum, row_start, cursor, n);
    fill_csr_k  <<<(e + 255) / 256, 256>>>(src, dst, cursor, csr_src, e);

    dim3 gemm_block(256);
    dim3 gemm_grid((n + GBM - 1) / GBM, HDIM / GBN);

    // encoder: feat = x @ enc_W + enc_b
    tgemm_k<<<gemm_grid, gemm_block>>>(x, enc_W, enc_b, nullptr, feat, n, DIN, HDIM);

    for (int l = 0; l < 3; l++) {
        // hw = (feat @ Wl) * dinv[row]
        tgemm_k<<<gemm_grid, gemm_block>>>(feat, W[l], nullptr, dinv, hw, n, HDIM, HDIM);
        // gather + self-loop + bias + relu (+ fused decoder on last layer)
        gcn_gather_k<<<n, 256>>>(hw, row_start, csr_src, dinv, bb[l],
                                 feat, dec_W, dec_b, out, l == 2);
    }
}